// round 3
// baseline (speedup 1.0000x reference)
#include <cuda_runtime.h>
#include <cstddef>

// ---------------- scratch (static __device__ globals; no allocations) ----------------
__device__ float g_x1[(size_t)64 * 64 * 112 * 112];   // 205 MB
__device__ float g_x2[(size_t)64 * 128 * 56 * 56];    // 102 MB
__device__ float g_x3[(size_t)64 * 256 * 28 * 28];    // 51 MB
__device__ float g_x4[(size_t)64 * 512 * 14 * 14];    // 26 MB
__device__ float g_mean[64 * 512];
__device__ float g_sent[64 * 512];
__device__ float g_img[64 * 512];
__device__ float g_feats[64 * 1024];
__device__ float g_h1[64 * 512];
__device__ float g_h2[64 * 512];

// ---------------- embedding masked mean ----------------
__global__ void embed_mean_k(const int* __restrict__ seq, const int* __restrict__ len,
                             const float* __restrict__ emb, float* __restrict__ mean) {
    const int b = blockIdx.x;
    const int L = len[b];
    __shared__ int s_idx[128];
    for (int i = threadIdx.x; i < 128; i += blockDim.x) s_idx[i] = seq[b * 128 + i];
    __syncthreads();
    const float inv = 1.0f / (float)L;
    for (int d = threadIdx.x; d < 512; d += blockDim.x) {
        float acc = 0.0f;
        for (int s = 0; s < L; s++) acc += emb[(size_t)s_idx[s] * 512 + d];
        mean[b * 512 + d] = acc * inv;
    }
}

// ---------------- generic small linear ----------------
__global__ void linear_k(const float* __restrict__ X, const float* __restrict__ W,
                         const float* __restrict__ bias, float* __restrict__ Y,
                         int K, int N, int relu) {
    const int j = blockIdx.x * blockDim.x + threadIdx.x;
    const int b = blockIdx.y;
    if (j >= N) return;
    const float* x = X + (size_t)b * K;
    float acc = bias[j];
    for (int k = 0; k < K; k++) acc = fmaf(x[k], W[(size_t)k * N + j], acc);
    if (relu && acc < 0.0f) acc = 0.0f;
    Y[(size_t)b * N + j] = acc;
}

// ---------------- direct strided 3x3 conv, stride 2, SAME ----------------
// Block: 64 cout x (8 rows x 16 cols) output tile, one image.
// Thread (cg=tid>>5, pg=tid&31): 8 couts x 4 consecutive output cols.
// Input tile split into even/odd columns (stride-2 conv) so the per-thread
// taps are contiguous -> conflict-free LDS.128, reused across all 3 kx taps.
template <int CIN, int COUT, int HIN, int WIN>
__global__ void __launch_bounds__(256) conv_k(const float* __restrict__ in,
                                              const float* __restrict__ w,
                                              const float* __restrict__ bias,
                                              float* __restrict__ out) {
    constexpr int HOUT = HIN / 2, WOUT = WIN / 2;
    constexpr int TH = 8, TW = 16;
    constexpr int COUT_BLK = 64;
    constexpr int CC = (CIN < 8) ? CIN : 8;   // cin chunk
    constexpr int IH = 2 * TH + 1;            // 17 input rows
    constexpr int IW = 2 * TW + 1;            // 33 input cols (17 even + 16 odd)
    constexpr int PITCH = 24;                 // row pitch (words): phase covers all 32 banks

    __shared__ __align__(16) float s_ev[CC][IH][PITCH];  // even input cols (17 used)
    __shared__ __align__(16) float s_od[CC][IH][PITCH];  // odd  input cols (16 used)
    __shared__ __align__(16) float s_w[CC][9][COUT_BLK];

    constexpr int TILESX = (WOUT + TW - 1) / TW;
    const int tile = blockIdx.x;
    const int ty0 = (tile / TILESX) * TH;
    const int tx0 = (tile % TILESX) * TW;
    const int cob = blockIdx.y * COUT_BLK;
    const int n = blockIdx.z;

    const int tid = threadIdx.x;
    const int cg = tid >> 5;          // 0..7 (uniform per warp -> broadcast weight loads)
    const int pg = tid & 31;
    const int lrow = pg >> 2;         // local output row 0..7
    const int lcol0 = (pg & 3) * 4;   // local output col base {0,4,8,12}

    float acc[8][4];
#pragma unroll
    for (int i = 0; i < 8; i++)
#pragma unroll
        for (int j = 0; j < 4; j++) acc[i][j] = 0.0f;

    const int iy0 = 2 * ty0;
    const int ix0 = 2 * tx0;
    const float* in_n = in + (size_t)n * CIN * HIN * WIN;

    for (int c0 = 0; c0 < CIN; c0 += CC) {
        if (c0) __syncthreads();
        // load input tile, splitting even/odd columns (zero-fill OOB)
        for (int idx = tid; idx < CC * IH * IW; idx += 256) {
            int c = idx / (IH * IW);
            int rem = idx - c * (IH * IW);
            int r = rem / IW;
            int x = rem - r * IW;
            int gy = iy0 + r, gx = ix0 + x;
            float v = 0.0f;
            if (gy < HIN && gx < WIN)
                v = in_n[(size_t)(c0 + c) * HIN * WIN + (size_t)gy * WIN + gx];
            if (x & 1) s_od[c][r][x >> 1] = v;
            else       s_ev[c][r][x >> 1] = v;
        }
        // load weights chunk: OIHW -> s_w[cin][k][cout]
        for (int idx = tid; idx < CC * 9 * COUT_BLK; idx += 256) {
            int c = idx / (9 * COUT_BLK);
            int rem = idx - c * (9 * COUT_BLK);
            int k = rem / COUT_BLK;
            int co = rem - k * COUT_BLK;
            s_w[c][k][co] = w[((size_t)(cob + co) * CIN + (c0 + c)) * 9 + k];
        }
        __syncthreads();

        for (int c = 0; c < CC; c++) {
#pragma unroll
            for (int ky = 0; ky < 3; ky++) {
                const int irow = 2 * lrow + ky;
                const float* pe = &s_ev[c][irow][lcol0];
                const float4 e4 = *(const float4*)pe;        // even cols lcol0..+3
                const float  e1 = pe[4];                     // even col  lcol0+4
                const float4 o4 = *(const float4*)&s_od[c][irow][lcol0];

                // taps per kx (kx=0: even t, kx=1: odd t, kx=2: even t+1)
                const float iv0[4] = {e4.x, e4.y, e4.z, e4.w};
                const float iv1[4] = {o4.x, o4.y, o4.z, o4.w};
                const float iv2[4] = {e4.y, e4.z, e4.w, e1};

#pragma unroll
                for (int kx = 0; kx < 3; kx++) {
                    const int k = ky * 3 + kx;
                    const float4 w0 = *(const float4*)&s_w[c][k][cg * 8];
                    const float4 w1 = *(const float4*)&s_w[c][k][cg * 8 + 4];
                    const float wv[8] = {w0.x, w0.y, w0.z, w0.w, w1.x, w1.y, w1.z, w1.w};
                    const float* iv = (kx == 0) ? iv0 : (kx == 1) ? iv1 : iv2;
#pragma unroll
                    for (int i = 0; i < 8; i++)
#pragma unroll
                        for (int j = 0; j < 4; j++)
                            acc[i][j] = fmaf(wv[i], iv[j], acc[i][j]);
                }
            }
        }
    }

    const int orow = ty0 + lrow;
    if (orow < HOUT) {
        float* out_n = out + (size_t)n * COUT * HOUT * WOUT;
#pragma unroll
        for (int i = 0; i < 8; i++) {
            const int co = cob + cg * 8 + i;
            const float bv = bias[co];
            float* op = out_n + (size_t)co * HOUT * WOUT + (size_t)orow * WOUT;
#pragma unroll
            for (int j = 0; j < 4; j++) {
                int oc = tx0 + lcol0 + j;
                if (oc < WOUT) {
                    float v = acc[i][j] + bv;
                    op[oc] = v > 0.0f ? v : 0.0f;
                }
            }
        }
    }
}

// ---------------- global average pool over 14x14 ----------------
__global__ void pool_k(const float* __restrict__ x, float* __restrict__ y) {
    const int idx = blockIdx.x * 8 + (threadIdx.x >> 5);
    const int lane = threadIdx.x & 31;
    const float* p = x + (size_t)idx * 196;
    float s = 0.0f;
    for (int i = lane; i < 196; i += 32) s += p[i];
#pragma unroll
    for (int o = 16; o; o >>= 1) s += __shfl_down_sync(0xFFFFFFFFu, s, o);
    if (lane == 0) y[idx] = s * (1.0f / 196.0f);
}

// ---------------- feats = concat(img, sent) ----------------
__global__ void concat_k(const float* __restrict__ img, const float* __restrict__ sent,
                         float* __restrict__ feats) {
    const int i = blockIdx.x * blockDim.x + threadIdx.x;
    const int b = i >> 10, j = i & 1023;
    feats[i] = (j < 512) ? img[b * 512 + j] : sent[b * 512 + (j - 512)];
}

// ---------------- launch ----------------
extern "C" void kernel_launch(void* const* d_in, const int* in_sizes, int n_in,
                              void* d_out, int out_size) {
    const float* images = (const float*)d_in[0];
    const int*   seq    = (const int*)d_in[1];
    const int*   len    = (const int*)d_in[2];
    const float* emb    = (const float*)d_in[4];
    const float* cw1    = (const float*)d_in[5];
    const float* cb1    = (const float*)d_in[6];
    const float* cw2    = (const float*)d_in[7];
    const float* cb2    = (const float*)d_in[8];
    const float* cw3    = (const float*)d_in[9];
    const float* cb3    = (const float*)d_in[10];
    const float* cw4    = (const float*)d_in[11];
    const float* cb4    = (const float*)d_in[12];
    const float* rnn_w  = (const float*)d_in[13];
    const float* rnn_b  = (const float*)d_in[14];
    const float* fc1_w  = (const float*)d_in[15];
    const float* fc1_b  = (const float*)d_in[16];
    const float* fc2_w  = (const float*)d_in[17];
    const float* fc2_b  = (const float*)d_in[18];
    const float* clf_w  = (const float*)d_in[19];
    const float* clf_b  = (const float*)d_in[20];
    float* out = (float*)d_out;

    float *x1, *x2, *x3, *x4, *mean, *sent, *img, *feats, *h1, *h2;
    cudaGetSymbolAddress((void**)&x1, g_x1);
    cudaGetSymbolAddress((void**)&x2, g_x2);
    cudaGetSymbolAddress((void**)&x3, g_x3);
    cudaGetSymbolAddress((void**)&x4, g_x4);
    cudaGetSymbolAddress((void**)&mean, g_mean);
    cudaGetSymbolAddress((void**)&sent, g_sent);
    cudaGetSymbolAddress((void**)&img, g_img);
    cudaGetSymbolAddress((void**)&feats, g_feats);
    cudaGetSymbolAddress((void**)&h1, g_h1);
    cudaGetSymbolAddress((void**)&h2, g_h2);

    // text branch
    embed_mean_k<<<64, 512>>>(seq, len, emb, mean);
    linear_k<<<dim3(2, 64), 256>>>(mean, rnn_w, rnn_b, sent, 512, 512, 0);

    // vision branch
    conv_k<3, 64, 224, 224><<<dim3(7 * 14, 1, 64), 256>>>(images, cw1, cb1, x1);
    conv_k<64, 128, 112, 112><<<dim3(4 * 7, 2, 64), 256>>>(x1, cw2, cb2, x2);
    conv_k<128, 256, 56, 56><<<dim3(2 * 4, 4, 64), 256>>>(x2, cw3, cb3, x3);
    conv_k<256, 512, 28, 28><<<dim3(1 * 2, 8, 64), 256>>>(x3, cw4, cb4, x4);
    pool_k<<<(64 * 512) / 8, 256>>>(x4, img);

    // head
    concat_k<<<(64 * 1024) / 256, 256>>>(img, sent, feats);
    linear_k<<<dim3(2, 64), 256>>>(feats, fc1_w, fc1_b, h1, 1024, 512, 1);
    linear_k<<<dim3(2, 64), 256>>>(h1, fc2_w, fc2_b, h2, 512, 512, 1);
    linear_k<<<dim3(4, 64), 256>>>(h2, clf_w, clf_b, out, 512, 1000, 0);
}

// round 4
// speedup vs baseline: 1.0325x; 1.0325x over previous
#include <cuda_runtime.h>
#include <cstddef>

typedef unsigned long long ull;

__device__ __forceinline__ ull pack2(float lo, float hi) {
    ull r; asm("mov.b64 %0, {%1, %2};" : "=l"(r) : "f"(lo), "f"(hi)); return r;
}
__device__ __forceinline__ void unpack2(ull v, float& lo, float& hi) {
    asm("mov.b64 {%0, %1}, %2;" : "=f"(lo), "=f"(hi) : "l"(v));
}
__device__ __forceinline__ void fma2(ull& d, ull a, ull b) {
    asm("fma.rn.f32x2 %0, %1, %2, %0;" : "+l"(d) : "l"(a), "l"(b));
}

// ---------------- scratch (static __device__ globals; no allocations) ----------------
__device__ float g_x1[(size_t)64 * 64 * 112 * 112];
__device__ float g_x2[(size_t)64 * 128 * 56 * 56];
__device__ float g_x3[(size_t)64 * 256 * 28 * 28];
__device__ float g_x4[(size_t)64 * 512 * 14 * 14];
__device__ float g_mean[64 * 512];
__device__ float g_sent[64 * 512];
__device__ float g_img[64 * 512];
__device__ float g_feats[64 * 1024];
__device__ float g_h1[64 * 512];
__device__ float g_h2[64 * 512];

// ---------------- embedding masked mean ----------------
__global__ void embed_mean_k(const int* __restrict__ seq, const int* __restrict__ len,
                             const float* __restrict__ emb, float* __restrict__ mean) {
    const int b = blockIdx.x;
    const int L = len[b];
    __shared__ int s_idx[128];
    for (int i = threadIdx.x; i < 128; i += blockDim.x) s_idx[i] = seq[b * 128 + i];
    __syncthreads();
    const float inv = 1.0f / (float)L;
    for (int d = threadIdx.x; d < 512; d += blockDim.x) {
        float acc = 0.0f;
        for (int s = 0; s < L; s++) acc += emb[(size_t)s_idx[s] * 512 + d];
        mean[b * 512 + d] = acc * inv;
    }
}

// ---------------- generic small linear ----------------
__global__ void linear_k(const float* __restrict__ X, const float* __restrict__ W,
                         const float* __restrict__ bias, float* __restrict__ Y,
                         int K, int N, int relu) {
    const int j = blockIdx.x * blockDim.x + threadIdx.x;
    const int b = blockIdx.y;
    if (j >= N) return;
    const float* x = X + (size_t)b * K;
    float acc = bias[j];
    for (int k = 0; k < K; k++) acc = fmaf(x[k], W[(size_t)k * N + j], acc);
    if (relu && acc < 0.0f) acc = 0.0f;
    Y[(size_t)b * N + j] = acc;
}

// ---------------- direct strided 3x3 conv, stride 2, SAME, packed f32x2 ----------------
// Block: 64 cout x (8 rows x 16 cols) output tile, one image.
// Thread: 8 couts (as 4 packed pairs) x 4 output cols.
// Weight pairs come pre-packed from LDS.128 (adjacent couts contiguous in s_w).
template <int CIN, int COUT, int HIN, int WIN>
__global__ void __launch_bounds__(256) conv_k(const float* __restrict__ in,
                                              const float* __restrict__ w,
                                              const float* __restrict__ bias,
                                              float* __restrict__ out) {
    constexpr int HOUT = HIN / 2, WOUT = WIN / 2;
    constexpr int TH = 8, TW = 16;
    constexpr int COUT_BLK = 64;
    constexpr int CC = (CIN < 8) ? CIN : 8;
    constexpr int IH = 2 * TH + 1;            // 17
    constexpr int IW = 2 * TW + 1;            // 33 (17 even + 16 odd)
    constexpr int PITCH = 24;                 // conflict-free vector-phase pitch

    __shared__ __align__(16) float s_ev[CC][IH][PITCH];
    __shared__ __align__(16) float s_od[CC][IH][PITCH];
    __shared__ __align__(16) float s_w[CC][9][COUT_BLK];

    constexpr int TILESX = (WOUT + TW - 1) / TW;
    const int tile = blockIdx.x;
    const int ty0 = (tile / TILESX) * TH;
    const int tx0 = (tile % TILESX) * TW;
    const int cob = blockIdx.y * COUT_BLK;
    const int n = blockIdx.z;

    const int tid = threadIdx.x;
    const int cg = tid >> 5;          // warp-uniform cout group
    const int pg = tid & 31;
    const int lrow = pg >> 2;
    const int lcol0 = (pg & 3) * 4;

    ull acc[4][4];                    // [cout-pair][col], each = 2 packed fp32
#pragma unroll
    for (int i = 0; i < 4; i++)
#pragma unroll
        for (int j = 0; j < 4; j++) acc[i][j] = 0ull;

    const int iy0 = 2 * ty0;
    const int ix0 = 2 * tx0;
    const float* in_n = in + (size_t)n * CIN * HIN * WIN;

    for (int c0 = 0; c0 < CIN; c0 += CC) {
        if (c0) __syncthreads();
        for (int idx = tid; idx < CC * IH * IW; idx += 256) {
            int c = idx / (IH * IW);
            int rem = idx - c * (IH * IW);
            int r = rem / IW;
            int x = rem - r * IW;
            int gy = iy0 + r, gx = ix0 + x;
            float v = 0.0f;
            if (gy < HIN && gx < WIN)
                v = in_n[(size_t)(c0 + c) * HIN * WIN + (size_t)gy * WIN + gx];
            if (x & 1) s_od[c][r][x >> 1] = v;
            else       s_ev[c][r][x >> 1] = v;
        }
        for (int idx = tid; idx < CC * 9 * COUT_BLK; idx += 256) {
            int c = idx / (9 * COUT_BLK);
            int rem = idx - c * (9 * COUT_BLK);
            int k = rem / COUT_BLK;
            int co = rem - k * COUT_BLK;
            s_w[c][k][co] = w[((size_t)(cob + co) * CIN + (c0 + c)) * 9 + k];
        }
        __syncthreads();

        for (int c = 0; c < CC; c++) {
#pragma unroll
            for (int ky = 0; ky < 3; ky++) {
                const int irow = 2 * lrow + ky;
                const float* pe = &s_ev[c][irow][lcol0];
                const float4 e4 = *(const float4*)pe;
                const float  e1 = pe[4];
                const float4 o4 = *(const float4*)&s_od[c][irow][lcol0];

                // duplicate each input tap into both packed lanes
                const ull dx = pack2(e4.x, e4.x), dy = pack2(e4.y, e4.y);
                const ull dz = pack2(e4.z, e4.z), dw = pack2(e4.w, e4.w);
                const ull d1 = pack2(e1, e1);
                const ull qx = pack2(o4.x, o4.x), qy = pack2(o4.y, o4.y);
                const ull qz = pack2(o4.z, o4.z), qw = pack2(o4.w, o4.w);

                const ull iv0[4] = {dx, dy, dz, dw};   // kx=0 (even)
                const ull iv1[4] = {qx, qy, qz, qw};   // kx=1 (odd)
                const ull iv2[4] = {dy, dz, dw, d1};   // kx=2 (even+1)

#pragma unroll
                for (int kx = 0; kx < 3; kx++) {
                    const int k = ky * 3 + kx;
                    // LDS.128 of 4 adjacent couts = 2 ready-packed f32x2 pairs
                    const ulonglong2 wA = *(const ulonglong2*)&s_w[c][k][cg * 8];
                    const ulonglong2 wB = *(const ulonglong2*)&s_w[c][k][cg * 8 + 4];
                    const ull wp[4] = {wA.x, wA.y, wB.x, wB.y};
                    const ull* iv = (kx == 0) ? iv0 : (kx == 1) ? iv1 : iv2;
#pragma unroll
                    for (int i = 0; i < 4; i++)
#pragma unroll
                        for (int j = 0; j < 4; j++)
                            fma2(acc[i][j], wp[i], iv[j]);
                }
            }
        }
    }

    const int orow = ty0 + lrow;
    if (orow < HOUT) {
        float* out_n = out + (size_t)n * COUT * HOUT * WOUT;
#pragma unroll
        for (int i = 0; i < 4; i++) {
            const int co0 = cob + cg * 8 + 2 * i;       // lo lane
            const float bv0 = bias[co0];
            const float bv1 = bias[co0 + 1];
            float* op0 = out_n + (size_t)co0 * HOUT * WOUT + (size_t)orow * WOUT;
            float* op1 = op0 + (size_t)HOUT * WOUT;
#pragma unroll
            for (int j = 0; j < 4; j++) {
                int oc = tx0 + lcol0 + j;
                if (oc < WOUT) {
                    float lo, hi;
                    unpack2(acc[i][j], lo, hi);
                    float v0 = lo + bv0;
                    float v1 = hi + bv1;
                    op0[oc] = v0 > 0.0f ? v0 : 0.0f;
                    op1[oc] = v1 > 0.0f ? v1 : 0.0f;
                }
            }
        }
    }
}

// ---------------- global average pool over 14x14 ----------------
__global__ void pool_k(const float* __restrict__ x, float* __restrict__ y) {
    const int idx = blockIdx.x * 8 + (threadIdx.x >> 5);
    const int lane = threadIdx.x & 31;
    const float* p = x + (size_t)idx * 196;
    float s = 0.0f;
    for (int i = lane; i < 196; i += 32) s += p[i];
#pragma unroll
    for (int o = 16; o; o >>= 1) s += __shfl_down_sync(0xFFFFFFFFu, s, o);
    if (lane == 0) y[idx] = s * (1.0f / 196.0f);
}

// ---------------- feats = concat(img, sent) ----------------
__global__ void concat_k(const float* __restrict__ img, const float* __restrict__ sent,
                         float* __restrict__ feats) {
    const int i = blockIdx.x * blockDim.x + threadIdx.x;
    const int b = i >> 10, j = i & 1023;
    feats[i] = (j < 512) ? img[b * 512 + j] : sent[b * 512 + (j - 512)];
}

// ---------------- launch ----------------
extern "C" void kernel_launch(void* const* d_in, const int* in_sizes, int n_in,
                              void* d_out, int out_size) {
    const float* images = (const float*)d_in[0];
    const int*   seq    = (const int*)d_in[1];
    const int*   len    = (const int*)d_in[2];
    const float* emb    = (const float*)d_in[4];
    const float* cw1    = (const float*)d_in[5];
    const float* cb1    = (const float*)d_in[6];
    const float* cw2    = (const float*)d_in[7];
    const float* cb2    = (const float*)d_in[8];
    const float* cw3    = (const float*)d_in[9];
    const float* cb3    = (const float*)d_in[10];
    const float* cw4    = (const float*)d_in[11];
    const float* cb4    = (const float*)d_in[12];
    const float* rnn_w  = (const float*)d_in[13];
    const float* rnn_b  = (const float*)d_in[14];
    const float* fc1_w  = (const float*)d_in[15];
    const float* fc1_b  = (const float*)d_in[16];
    const float* fc2_w  = (const float*)d_in[17];
    const float* fc2_b  = (const float*)d_in[18];
    const float* clf_w  = (const float*)d_in[19];
    const float* clf_b  = (const float*)d_in[20];
    float* out = (float*)d_out;

    float *x1, *x2, *x3, *x4, *mean, *sent, *img, *feats, *h1, *h2;
    cudaGetSymbolAddress((void**)&x1, g_x1);
    cudaGetSymbolAddress((void**)&x2, g_x2);
    cudaGetSymbolAddress((void**)&x3, g_x3);
    cudaGetSymbolAddress((void**)&x4, g_x4);
    cudaGetSymbolAddress((void**)&mean, g_mean);
    cudaGetSymbolAddress((void**)&sent, g_sent);
    cudaGetSymbolAddress((void**)&img, g_img);
    cudaGetSymbolAddress((void**)&feats, g_feats);
    cudaGetSymbolAddress((void**)&h1, g_h1);
    cudaGetSymbolAddress((void**)&h2, g_h2);

    // text branch
    embed_mean_k<<<64, 512>>>(seq, len, emb, mean);
    linear_k<<<dim3(2, 64), 256>>>(mean, rnn_w, rnn_b, sent, 512, 512, 0);

    // vision branch
    conv_k<3, 64, 224, 224><<<dim3(7 * 14, 1, 64), 256>>>(images, cw1, cb1, x1);
    conv_k<64, 128, 112, 112><<<dim3(4 * 7, 2, 64), 256>>>(x1, cw2, cb2, x2);
    conv_k<128, 256, 56, 56><<<dim3(2 * 4, 4, 64), 256>>>(x2, cw3, cb3, x3);
    conv_k<256, 512, 28, 28><<<dim3(1 * 2, 8, 64), 256>>>(x3, cw4, cb4, x4);
    pool_k<<<(64 * 512) / 8, 256>>>(x4, img);

    // head
    concat_k<<<(64 * 1024) / 256, 256>>>(img, sent, feats);
    linear_k<<<dim3(2, 64), 256>>>(feats, fc1_w, fc1_b, h1, 1024, 512, 1);
    linear_k<<<dim3(2, 64), 256>>>(h1, fc2_w, fc2_b, h2, 512, 512, 1);
    linear_k<<<dim3(4, 64), 256>>>(h2, clf_w, clf_b, out, 512, 1000, 0);
}

// round 6
// speedup vs baseline: 2.9560x; 2.8629x over previous
#include <cuda_runtime.h>
#include <cuda_bf16.h>
#include <cstdint>
#include <cstddef>

typedef __nv_bfloat16 bf16;

// ============================ helpers ============================
__device__ __forceinline__ uint32_t smem_u32(const void* p) {
    uint32_t a;
    asm("{ .reg .u64 t; cvta.to.shared.u64 t, %1; cvt.u32.u64 %0, t; }" : "=r"(a) : "l"(p));
    return a;
}
__device__ __forceinline__ void ldsm4(uint32_t& r0, uint32_t& r1, uint32_t& r2, uint32_t& r3,
                                      uint32_t addr) {
    asm volatile("ldmatrix.sync.aligned.m8n8.x4.shared.b16 {%0,%1,%2,%3}, [%4];"
                 : "=r"(r0), "=r"(r1), "=r"(r2), "=r"(r3) : "r"(addr));
}
__device__ __forceinline__ void mma16816(float c[4], const uint32_t a[4], const uint32_t b[2]) {
    asm volatile(
        "mma.sync.aligned.m16n8k16.row.col.f32.bf16.bf16.f32 "
        "{%0,%1,%2,%3}, {%4,%5,%6,%7}, {%8,%9}, {%0,%1,%2,%3};"
        : "+f"(c[0]), "+f"(c[1]), "+f"(c[2]), "+f"(c[3])
        : "r"(a[0]), "r"(a[1]), "r"(a[2]), "r"(a[3]), "r"(b[0]), "r"(b[1]));
}
__device__ __forceinline__ void bsplit(float v, bf16& h, bf16& l) {
    h = __float2bfloat16(v);
    l = __float2bfloat16(v - __bfloat162float(h));
}

// smem tile pitch: 72 bf16 (144 B) -> row stride 36 words -> ldmatrix conflict-free
static constexpr int PITCH = 72;
static constexpr int ATILE_B = 128 * PITCH * 2;   // 18432 bytes per 128x64 bf16 tile

// ============================ scratch ============================
__device__ bf16 g_x1h[(size_t)64 * 112 * 112 * 64];
__device__ bf16 g_x1l[(size_t)64 * 112 * 112 * 64];
__device__ bf16 g_x2h[(size_t)64 * 56 * 56 * 128];
__device__ bf16 g_x2l[(size_t)64 * 56 * 56 * 128];
__device__ bf16 g_x3h[(size_t)64 * 28 * 28 * 256];
__device__ bf16 g_x3l[(size_t)64 * 28 * 28 * 256];
__device__ bf16 g_x4h[(size_t)64 * 14 * 14 * 512];
__device__ bf16 g_x4l[(size_t)64 * 14 * 14 * 512];
__device__ bf16 g_w1h[64 * 64], g_w1l[64 * 64];              // conv1 padded [co][64]
__device__ bf16 g_w2h[9 * 128 * 64],  g_w2l[9 * 128 * 64];   // [t][co][ci]
__device__ bf16 g_w3h[9 * 256 * 128], g_w3l[9 * 256 * 128];
__device__ bf16 g_w4h[9 * 512 * 256], g_w4l[9 * 512 * 256];
__device__ float g_mean[64 * 512];
__device__ float g_sent[64 * 512];
__device__ float g_img[64 * 512];
__device__ float g_feats[64 * 1024];
__device__ float g_h1[64 * 512];
__device__ float g_h2[64 * 512];

// ============================ weight prep ============================
__global__ void wprep1_k(const float* __restrict__ w, bf16* __restrict__ wh, bf16* __restrict__ wl) {
    int idx = blockIdx.x * 256 + threadIdx.x;      // 64*64
    if (idx >= 64 * 64) return;
    int co = idx >> 6, k = idx & 63;
    float v = (k < 27) ? w[co * 27 + k] : 0.0f;
    bf16 h, l; bsplit(v, h, l);
    wh[idx] = h; wl[idx] = l;
}
__global__ void wprepT_k(const float* __restrict__ w, bf16* __restrict__ wh, bf16* __restrict__ wl,
                         int COUT, int CIN) {
    int idx = blockIdx.x * 256 + threadIdx.x;      // COUT*CIN*9
    if (idx >= COUT * CIN * 9) return;
    int co = idx / (CIN * 9);
    int rem = idx - co * (CIN * 9);
    int ci = rem / 9, t = rem - ci * 9;
    bf16 h, l; bsplit(w[idx], h, l);
    int o = (t * COUT + co) * CIN + ci;
    wh[o] = h; wl[o] = l;
}

// ============================ warp-level GEMM core ============================
// one 64-wide k chunk: c += Ah*Bh^T + Ah*Bl^T + Al*Bh^T  (3-term bf16 split)
template <int NFRAG>
__device__ __forceinline__ void chunk_mma(uint32_t sbA_h, uint32_t sbA_l,
                                          uint32_t sbB_h, uint32_t sbB_l,
                                          int lane, int warpM, int warpN,
                                          float (&c)[2][NFRAG][4]) {
    const int arow = warpM * 32 + (lane & 15);
    const int akoff = (lane >> 4) * 8;
    const int brow = warpN * (NFRAG * 8) + (lane & 7) + ((lane >> 3) & 1) * 8;
    const int bkoff = (lane >> 4) * 8;
#pragma unroll
    for (int ks = 0; ks < 4; ks++) {
        const int k0 = ks * 16;
        uint32_t ah[2][4], al[2][4];
#pragma unroll
        for (int i = 0; i < 2; i++) {
            const uint32_t aoff = (((arow + i * 16) * PITCH) + k0 + akoff) * 2;
            ldsm4(ah[i][0], ah[i][1], ah[i][2], ah[i][3], sbA_h + aoff);
            ldsm4(al[i][0], al[i][1], al[i][2], al[i][3], sbA_l + aoff);
        }
        uint32_t bh[NFRAG][2], bl[NFRAG][2];
#pragma unroll
        for (int j2 = 0; j2 < NFRAG / 2; j2++) {
            const uint32_t boff = (((brow + j2 * 16) * PITCH) + k0 + bkoff) * 2;
            uint32_t r0, r1, r2, r3;
            ldsm4(r0, r1, r2, r3, sbB_h + boff);
            bh[2 * j2][0] = r0; bh[2 * j2][1] = r2;
            bh[2 * j2 + 1][0] = r1; bh[2 * j2 + 1][1] = r3;
            ldsm4(r0, r1, r2, r3, sbB_l + boff);
            bl[2 * j2][0] = r0; bl[2 * j2][1] = r2;
            bl[2 * j2 + 1][0] = r1; bl[2 * j2 + 1][1] = r3;
        }
#pragma unroll
        for (int i = 0; i < 2; i++)
#pragma unroll
            for (int j = 0; j < NFRAG; j++) {
                mma16816(c[i][j], ah[i], bh[j]);
                mma16816(c[i][j], ah[i], bl[j]);
                mma16816(c[i][j], al[i], bh[j]);
            }
    }
}

// epilogue: bias + relu + bsplit -> NHWC hi/lo
template <int NFRAG, int COUT>
__device__ __forceinline__ void epilogue(float (&c)[2][NFRAG][4], const float* __restrict__ bias,
                                         int tile0, int cob, int lane, int warpM, int warpN,
                                         bf16* __restrict__ yh, bf16* __restrict__ yl) {
#pragma unroll
    for (int i = 0; i < 2; i++) {
        const int r0 = tile0 + warpM * 32 + i * 16 + (lane >> 2);
#pragma unroll
        for (int j = 0; j < NFRAG; j++) {
            const int col = cob + warpN * (NFRAG * 8) + j * 8 + (lane & 3) * 2;
            const float b0 = bias[col], b1 = bias[col + 1];
#pragma unroll
            for (int h = 0; h < 2; h++) {
                const int r = r0 + h * 8;
                float v0 = c[i][j][2 * h + 0] + b0; if (v0 < 0.0f) v0 = 0.0f;
                float v1 = c[i][j][2 * h + 1] + b1; if (v1 < 0.0f) v1 = 0.0f;
                bf16 h0, l0, h1, l1;
                bsplit(v0, h0, l0); bsplit(v1, h1, l1);
                const size_t o = (size_t)r * COUT + col;
                __nv_bfloat162 ph, pl;
                ph.x = h0; ph.y = h1; pl.x = l0; pl.y = l1;
                *(__nv_bfloat162*)(yh + o) = ph;
                *(__nv_bfloat162*)(yl + o) = pl;
            }
        }
    }
}

// ============================ conv2/3/4: implicit GEMM ============================
template <int CIN, int COUT, int HIN, int WIN>
__global__ void __launch_bounds__(256, 2)
convmm_k(const bf16* __restrict__ xh, const bf16* __restrict__ xl,
         const bf16* __restrict__ wth, const bf16* __restrict__ wtl,
         const float* __restrict__ bias,
         bf16* __restrict__ yh, bf16* __restrict__ yl) {
    constexpr int HOUT = HIN / 2, WOUT = WIN / 2;
    constexpr int CPT = CIN / 64;
    constexpr int NCH = 9 * CPT;
    constexpr int NFRAG = 8;

    extern __shared__ char sb[];
    const uint32_t sb32 = smem_u32(sb);
    const uint32_t oAh = 0, oAl = ATILE_B, oBh = 2 * ATILE_B, oBl = 3 * ATILE_B;

    const int tid = threadIdx.x, lane = tid & 31, wid = tid >> 5;
    const int warpM = wid >> 1, warpN = wid & 1;
    const int tile0 = blockIdx.x * 128;
    const int cob = blockIdx.y * 128;

    // staging coords: 4 slots per thread; row = (tid>>3)+32*r4, c16 = tid&7
    const int c16 = tid & 7;
    int baseoff[4]; bool xe[4], ye[4];
#pragma unroll
    for (int r4 = 0; r4 < 4; r4++) {
        const int row = (tid >> 3) + 32 * r4;
        const int s = tile0 + row;
        const int n = s / (HOUT * WOUT);
        const int rem = s - n * (HOUT * WOUT);
        const int y = rem / WOUT;
        const int x = rem - y * WOUT;
        baseoff[r4] = ((n * HIN + 2 * y) * WIN + 2 * x) * CIN;
        xe[r4] = (2 * x + 2 >= WIN);
        ye[r4] = (2 * y + 2 >= HIN);
    }

    float c[2][NFRAG][4];
#pragma unroll
    for (int i = 0; i < 2; i++)
#pragma unroll
        for (int j = 0; j < NFRAG; j++)
#pragma unroll
            for (int q = 0; q < 4; q++) c[i][j][q] = 0.0f;

    for (int ch = 0; ch < NCH; ch++) {
        const int t = ch / CPT;
        const int cb = (ch - t * CPT) * 64;
        const int ky = t / 3, kx = t - ky * 3;
        __syncthreads();   // protect smem from previous chunk's readers
#pragma unroll
        for (int r4 = 0; r4 < 4; r4++) {
            const int row = (tid >> 3) + 32 * r4;
            const uint32_t soff = (row * PITCH + c16 * 8) * 2;
            const bool valid = !((kx == 2 && xe[r4]) || (ky == 2 && ye[r4]));
            const size_t src = (size_t)baseoff[r4] + (ky * WIN + kx) * CIN + cb + c16 * 8;
            uint4 vh = make_uint4(0, 0, 0, 0), vl = make_uint4(0, 0, 0, 0);
            if (valid) { vh = *(const uint4*)(xh + src); vl = *(const uint4*)(xl + src); }
            *(uint4*)(sb + oAh + soff) = vh;
            *(uint4*)(sb + oAl + soff) = vl;
            const size_t wsrc = ((size_t)t * COUT + cob + row) * CIN + cb + c16 * 8;
            *(uint4*)(sb + oBh + soff) = *(const uint4*)(wth + wsrc);
            *(uint4*)(sb + oBl + soff) = *(const uint4*)(wtl + wsrc);
        }
        __syncthreads();
        chunk_mma<NFRAG>(sb32 + oAh, sb32 + oAl, sb32 + oBh, sb32 + oBl,
                         lane, warpM, warpN, c);
    }

    epilogue<NFRAG, COUT>(c, bias, tile0, cob, lane, warpM, warpN, yh, yl);
}

// ============================ conv1: implicit GEMM, K=27 (padded 64) ============================
__global__ void __launch_bounds__(256, 2)
conv1mm_k(const float* __restrict__ images,
          const bf16* __restrict__ wh, const bf16* __restrict__ wl,
          const float* __restrict__ bias,
          bf16* __restrict__ yh, bf16* __restrict__ yl) {
    constexpr int HOUT = 112, WOUT = 112, HIN = 224, WIN = 224;
    constexpr int NFRAG = 4;   // 64 couts: warp tile 32x32

    extern __shared__ char sb[];
    const uint32_t sb32 = smem_u32(sb);
    const uint32_t oAh = 0, oAl = ATILE_B, oBh = 2 * ATILE_B;
    const uint32_t oBl = 2 * ATILE_B + 64 * PITCH * 2;

    const int tid = threadIdx.x, lane = tid & 31, wid = tid >> 5;
    const int warpM = wid >> 1, warpN = wid & 1;
    const int tile0 = blockIdx.x * 128;

    // A staging: thread owns k = tid&63, rows (tid>>6)+4i
    {
        const int k = tid & 63;
        const int r0 = tid >> 6;
        int ci = 0, ky = 0, kx = 0;
        const bool kvalid = (k < 27);
        if (kvalid) { ci = k / 9; int r = k - ci * 9; ky = r / 3; kx = r - ky * 3; }
        for (int i = 0; i < 32; i++) {
            const int row = r0 + 4 * i;
            bf16 h = __float2bfloat16(0.0f), l = __float2bfloat16(0.0f);
            if (kvalid) {
                const int s = tile0 + row;
                const int n = s / (HOUT * WOUT);
                const int rem = s - n * (HOUT * WOUT);
                const int y = rem / WOUT;
                const int x = rem - y * WOUT;
                const int iy = 2 * y + ky, ix = 2 * x + kx;
                if (iy < HIN && ix < WIN) {
                    float v = images[((size_t)(n * 3 + ci) * HIN + iy) * WIN + ix];
                    bsplit(v, h, l);
                }
            }
            const uint32_t soff = (row * PITCH + k) * 2;
            *(bf16*)(sb + oAh + soff) = h;
            *(bf16*)(sb + oAl + soff) = l;
        }
    }
    // B staging: 64 rows x 8 c16
    for (int idx = tid; idx < 512; idx += 256) {
        const int row = idx >> 3, c16 = idx & 7;
        const uint32_t soff = (row * PITCH + c16 * 8) * 2;
        *(uint4*)(sb + oBh + soff) = *(const uint4*)(wh + row * 64 + c16 * 8);
        *(uint4*)(sb + oBl + soff) = *(const uint4*)(wl + row * 64 + c16 * 8);
    }
    __syncthreads();

    float c[2][NFRAG][4];
#pragma unroll
    for (int i = 0; i < 2; i++)
#pragma unroll
        for (int j = 0; j < NFRAG; j++)
#pragma unroll
            for (int q = 0; q < 4; q++) c[i][j][q] = 0.0f;

    chunk_mma<NFRAG>(sb32 + oAh, sb32 + oAl, sb32 + oBh, sb32 + oBl,
                     lane, warpM, warpN, c);

    epilogue<NFRAG, 64>(c, bias, tile0, 0, lane, warpM, warpN, yh, yl);
}

// ============================ misc kernels ============================
__global__ void embed_mean_k(const int* __restrict__ seq, const int* __restrict__ len,
                             const float* __restrict__ emb, float* __restrict__ mean) {
    const int b = blockIdx.x;
    const int L = len[b];
    __shared__ int s_idx[128];
    for (int i = threadIdx.x; i < 128; i += blockDim.x) s_idx[i] = seq[b * 128 + i];
    __syncthreads();
    const float inv = 1.0f / (float)L;
    for (int d = threadIdx.x; d < 512; d += blockDim.x) {
        float acc = 0.0f;
        for (int s = 0; s < L; s++) acc += emb[(size_t)s_idx[s] * 512 + d];
        mean[b * 512 + d] = acc * inv;
    }
}

__global__ void linear_k(const float* __restrict__ X, const float* __restrict__ W,
                         const float* __restrict__ bias, float* __restrict__ Y,
                         int K, int N, int relu) {
    const int j = blockIdx.x * blockDim.x + threadIdx.x;
    const int b = blockIdx.y;
    if (j >= N) return;
    const float* x = X + (size_t)b * K;
    float acc = bias[j];
    for (int k = 0; k < K; k++) acc = fmaf(x[k], W[(size_t)k * N + j], acc);
    if (relu && acc < 0.0f) acc = 0.0f;
    Y[(size_t)b * N + j] = acc;
}

// pool over 196 spatial (NHWC hi/lo), thread per (n,c)
__global__ void pool2_k(const bf16* __restrict__ xh, const bf16* __restrict__ xl,
                        float* __restrict__ y) {
    const int idx = blockIdx.x * 256 + threadIdx.x;   // 64*512
    const int n = idx >> 9, c = idx & 511;
    const bf16* ph = xh + (size_t)n * 196 * 512 + c;
    const bf16* pl = xl + (size_t)n * 196 * 512 + c;
    float s = 0.0f;
    for (int p = 0; p < 196; p++)
        s += __bfloat162float(ph[(size_t)p * 512]) + __bfloat162float(pl[(size_t)p * 512]);
    y[idx] = s * (1.0f / 196.0f);
}

__global__ void concat_k(const float* __restrict__ img, const float* __restrict__ sent,
                         float* __restrict__ feats) {
    const int i = blockIdx.x * blockDim.x + threadIdx.x;
    const int b = i >> 10, j = i & 1023;
    feats[i] = (j < 512) ? img[b * 512 + j] : sent[b * 512 + (j - 512)];
}

// ============================ launch ============================
extern "C" void kernel_launch(void* const* d_in, const int* in_sizes, int n_in,
                              void* d_out, int out_size) {
    const float* images = (const float*)d_in[0];
    const int*   seq    = (const int*)d_in[1];
    const int*   len    = (const int*)d_in[2];
    const float* emb    = (const float*)d_in[4];
    const float* cw1 = (const float*)d_in[5],  *cb1 = (const float*)d_in[6];
    const float* cw2 = (const float*)d_in[7],  *cb2 = (const float*)d_in[8];
    const float* cw3 = (const float*)d_in[9],  *cb3 = (const float*)d_in[10];
    const float* cw4 = (const float*)d_in[11], *cb4 = (const float*)d_in[12];
    const float* rnn_w = (const float*)d_in[13], *rnn_b = (const float*)d_in[14];
    const float* fc1_w = (const float*)d_in[15], *fc1_b = (const float*)d_in[16];
    const float* fc2_w = (const float*)d_in[17], *fc2_b = (const float*)d_in[18];
    const float* clf_w = (const float*)d_in[19], *clf_b = (const float*)d_in[20];
    float* out = (float*)d_out;

    bf16 *x1h, *x1l, *x2h, *x2l, *x3h, *x3l, *x4h, *x4l;
    bf16 *w1h, *w1l, *w2h, *w2l, *w3h, *w3l, *w4h, *w4l;
    float *mean, *sent, *img, *feats, *h1, *h2;
    cudaGetSymbolAddress((void**)&x1h, g_x1h); cudaGetSymbolAddress((void**)&x1l, g_x1l);
    cudaGetSymbolAddress((void**)&x2h, g_x2h); cudaGetSymbolAddress((void**)&x2l, g_x2l);
    cudaGetSymbolAddress((void**)&x3h, g_x3h); cudaGetSymbolAddress((void**)&x3l, g_x3l);
    cudaGetSymbolAddress((void**)&x4h, g_x4h); cudaGetSymbolAddress((void**)&x4l, g_x4l);
    cudaGetSymbolAddress((void**)&w1h, g_w1h); cudaGetSymbolAddress((void**)&w1l, g_w1l);
    cudaGetSymbolAddress((void**)&w2h, g_w2h); cudaGetSymbolAddress((void**)&w2l, g_w2l);
    cudaGetSymbolAddress((void**)&w3h, g_w3h); cudaGetSymbolAddress((void**)&w3l, g_w3l);
    cudaGetSymbolAddress((void**)&w4h, g_w4h); cudaGetSymbolAddress((void**)&w4l, g_w4l);
    cudaGetSymbolAddress((void**)&mean, g_mean); cudaGetSymbolAddress((void**)&sent, g_sent);
    cudaGetSymbolAddress((void**)&img, g_img);   cudaGetSymbolAddress((void**)&feats, g_feats);
    cudaGetSymbolAddress((void**)&h1, g_h1);     cudaGetSymbolAddress((void**)&h2, g_h2);

    const int smem234 = 4 * ATILE_B;                   // 73728
    const int smem1 = 2 * ATILE_B + 2 * 64 * PITCH * 2; // 55296
    cudaFuncSetAttribute(conv1mm_k, cudaFuncAttributeMaxDynamicSharedMemorySize, smem1);
    cudaFuncSetAttribute(convmm_k<64, 128, 112, 112>, cudaFuncAttributeMaxDynamicSharedMemorySize, smem234);
    cudaFuncSetAttribute(convmm_k<128, 256, 56, 56>,  cudaFuncAttributeMaxDynamicSharedMemorySize, smem234);
    cudaFuncSetAttribute(convmm_k<256, 512, 28, 28>,  cudaFuncAttributeMaxDynamicSharedMemorySize, smem234);

    // weight prep
    wprep1_k<<<16, 256>>>(cw1, w1h, w1l);
    wprepT_k<<<(128 * 64 * 9 + 255) / 256, 256>>>(cw2, w2h, w2l, 128, 64);
    wprepT_k<<<(256 * 128 * 9 + 255) / 256, 256>>>(cw3, w3h, w3l, 256, 128);
    wprepT_k<<<(512 * 256 * 9 + 255) / 256, 256>>>(cw4, w4h, w4l, 512, 256);

    // text branch
    embed_mean_k<<<64, 512>>>(seq, len, emb, mean);
    linear_k<<<dim3(2, 64), 256>>>(mean, rnn_w, rnn_b, sent, 512, 512, 0);

    // vision branch (implicit GEMM, NHWC bf16 hi/lo, mma.sync)
    conv1mm_k<<<6272, 256, smem1>>>(images, w1h, w1l, cb1, x1h, x1l);
    convmm_k<64, 128, 112, 112><<<dim3(1568, 1), 256, smem234>>>(x1h, x1l, w2h, w2l, cb2, x2h, x2l);
    convmm_k<128, 256, 56, 56><<<dim3(392, 2), 256, smem234>>>(x2h, x2l, w3h, w3l, cb3, x3h, x3l);
    convmm_k<256, 512, 28, 28><<<dim3(98, 4), 256, smem234>>>(x3h, x3l, w4h, w4l, cb4, x4h, x4l);
    pool2_k<<<128, 256>>>(x4h, x4l, img);

    // head
    concat_k<<<(64 * 1024) / 256, 256>>>(img, sent, feats);
    linear_k<<<dim3(2, 64), 256>>>(feats, fc1_w, fc1_b, h1, 1024, 512, 1);
    linear_k<<<dim3(2, 64), 256>>>(h1, fc2_w, fc2_b, h2, 512, 512, 1);
    linear_k<<<dim3(4, 64), 256>>>(h2, clf_w, clf_b, out, 512, 1000, 0);
}